// round 10
// baseline (speedup 1.0000x reference)
#include <cuda_runtime.h>
#include <cuda_bf16.h>
#include <mma.h>
#include <float.h>
#include <math.h>
#include <stdint.h>

#define NCH 65536
#define BB  64
#define LL  512
#define MS  8
#define HID 128

__device__ int g_selidx[(size_t)NCH * MS];
__device__ int g_seln[NCH];
__device__ __nv_bfloat16 g_w1hi[577 * 128];
__device__ __nv_bfloat16 g_w1lo[577 * 128];

using namespace nvcuda;

// order-preserving float->u32 (monotonic); masked entries use 0
__device__ __forceinline__ unsigned f2u(float f) {
    unsigned u = __float_as_uint(f);
    return (u & 0x80000000u) ? ~u : (u | 0x80000000u);
}

// ---------------------------------------------------------------------------
// W1 split: fp32 -> bf16 hi + lo (residual). Tiny.
// ---------------------------------------------------------------------------
__global__ void w1split_kernel(const float* __restrict__ W1)
{
    const int n = 577 * 128;
    for (int i = blockIdx.x * blockDim.x + threadIdx.x; i < n;
         i += gridDim.x * blockDim.x) {
        float f = W1[i];
        __nv_bfloat16 h = __float2bfloat16(f);
        g_w1hi[i] = h;
        g_w1lo[i] = __float2bfloat16(f - __bfloat162float(h));
    }
}

// ---------------------------------------------------------------------------
// Kernel 0: top-8 selection. grid 2048 x 256 thr; warp = 4 chains.
// ---------------------------------------------------------------------------
__global__ __launch_bounds__(256) void select_kernel(
    const int* __restrict__ mask, const float* __restrict__ rank)
{
    const int tid = threadIdx.x;
    const int w = tid >> 5, lane = tid & 31;
    const unsigned full = 0xffffffffu;

    for (int cc = 0; cc < 4; cc++) {
        const int chain = (blockIdx.x * 8 + w) * 4 + cc;
        const float* sc = rank + (size_t)chain * 512 + lane * 16;
        const int4*  mk = reinterpret_cast<const int4*>(
                              mask + (size_t)chain * 512) + lane * 4;
        unsigned key[16];
        unsigned m1 = 0, m2 = 0, m3 = 0;
        int p1 = 0, p2 = 0, p3 = 0;
        int cnt = 0;
#pragma unroll
        for (int g = 0; g < 4; g++) {
            int4   mw = mk[g];
            float4 s  = *reinterpret_cast<const float4*>(sc + g * 4);
            int   me[4] = {mw.x, mw.y, mw.z, mw.w};
            float vv[4] = {s.x, s.y, s.z, s.w};
#pragma unroll
            for (int e = 0; e < 4; e++) {
                const int i = g * 4 + e;
                bool mm = (me[e] != 0);
                unsigned k = mm ? f2u(vv[e]) : 0u;
                key[i] = k;
                cnt += mm ? 1 : 0;
                bool g1 = k > m1, g2 = k > m2, g3 = k > m3;
                m3 = g3 ? (g2 ? m2 : k) : m3;  p3 = g3 ? (g2 ? p2 : i) : p3;
                m2 = g2 ? (g1 ? m1 : k) : m2;  p2 = g2 ? (g1 ? p1 : i) : p2;
                m1 = g1 ? k : m1;              p1 = g1 ? i : p1;
            }
        }
        int tot  = __reduce_add_sync(full, cnt);
        int nsel = tot < 8 ? tot : 8;

        unsigned cons = 0;
#pragma unroll
        for (int t = 0; t < 8; t++) {
            unsigned m = __reduce_max_sync(full, m1);
            unsigned bal = __ballot_sync(full, m1 == m);
            int src = __ffs(bal) - 1;
            if (m != 0u && lane == src) {
                cons |= 1u << p1;
                m1 = m2; p1 = p2; m2 = m3; p2 = p3; m3 = 0; p3 = 0;
                if (m1 == 0u) {   // rare rescan
#pragma unroll
                    for (int i = 0; i < 16; i++) {
                        unsigned k = ((cons >> i) & 1u) ? 0u : key[i];
                        bool g1 = k > m1, g2 = k > m2, g3 = k > m3;
                        m3 = g3 ? (g2 ? m2 : k) : m3;  p3 = g3 ? (g2 ? p2 : i) : p3;
                        m2 = g2 ? (g1 ? m1 : k) : m2;  p2 = g2 ? (g1 ? p1 : i) : p2;
                        m1 = g1 ? k : m1;              p1 = g1 ? i : p1;
                    }
                }
            }
        }

        int my = __popc(cons);
        int pre = my;
#pragma unroll
        for (int off = 1; off < 32; off <<= 1) {
            int v = __shfl_up_sync(full, pre, off);
            if (lane >= off) pre += v;
        }
        pre -= my;
        if (lane == 0) g_seln[chain] = nsel;
        unsigned c = cons;
        int s = pre;
        while (c) {
            int i = __ffs(c) - 1;
            c &= c - 1;
            g_selidx[(size_t)chain * 8 + s] = lane * 16 + i;
            s++;
        }
    }
}

// ---------------------------------------------------------------------------
// Kernel 1 (fused): full MLP per 128 chains. K=577 in 9 chunks of 64:
// chunk 0 = q, chunks 1..8 = gathered k rows (slot jj), zero if jj >= nsel.
// WMMA bf16x3, fp32 acc. Epilogue: +b1 +logc*W1[576], gelu, dot W2 -> out.
// grid 512 x 256 threads.
// ---------------------------------------------------------------------------
#define A_LD 72
#define B_LD 136
#define OFF_AH 0
#define OFF_AL 18432
#define OFF_BH 36864
#define OFF_BL 54272
#define STG_LD 132
#define OFF_META 71680
// meta layout (floats/ints after OFF_META):
//   sBatch[128] int, sN[128] int, sLogc[128] f, sIdx[128*8] int,
//   sB1[128] f, sWl[128] f, sW2[128] f
#define FUSED_SMEM (71680 + 128*4*3 + 128*8*4 + 128*4*3)

__global__ __launch_bounds__(256, 2) void fused_mlp_kernel(
    const float* __restrict__ q,
    const float* __restrict__ kmat,
    const int*   __restrict__ batch_idx,
    const int*   __restrict__ count,
    const float* __restrict__ W1,
    const float* __restrict__ b1,
    const float* __restrict__ W2,
    const float* __restrict__ b2,
    float* __restrict__ out)
{
    extern __shared__ char smem[];
    __nv_bfloat16* Ah = reinterpret_cast<__nv_bfloat16*>(smem + OFF_AH);
    __nv_bfloat16* Al = reinterpret_cast<__nv_bfloat16*>(smem + OFF_AL);
    __nv_bfloat16* Bh = reinterpret_cast<__nv_bfloat16*>(smem + OFF_BH);
    __nv_bfloat16* Bl = reinterpret_cast<__nv_bfloat16*>(smem + OFF_BL);
    int*   sBatch = reinterpret_cast<int*>(smem + OFF_META);
    int*   sN     = sBatch + 128;
    float* sLogc  = reinterpret_cast<float*>(sN + 128);
    int*   sIdx   = reinterpret_cast<int*>(sLogc + 128);       // [128][8]
    float* sB1    = reinterpret_cast<float*>(sIdx + 1024);
    float* sWl    = sB1 + 128;
    float* sW2    = sWl + 128;

    const int tid = threadIdx.x;
    const int c0  = blockIdx.x * 128;

    if (tid < 128) {
        sBatch[tid] = batch_idx[c0 + tid];
        sN[tid]     = g_seln[c0 + tid];
        sLogc[tid]  = log1pf((float)count[c0 + tid]);
        sB1[tid]    = b1[tid];
        sWl[tid]    = W1[576 * 128 + tid];
        sW2[tid]    = W2[tid];
    }
    // sIdx: 1024 ints, 4 per thread
#pragma unroll
    for (int s = 0; s < 4; s++)
        sIdx[tid * 4 + s] = g_selidx[(size_t)c0 * 8 + tid * 4 + s];
    __syncthreads();

    const int w  = tid >> 5;
    const int wm = w >> 1, wn = w & 1;

    wmma::fragment<wmma::accumulator, 16, 16, 16, float> acc[2][4];
#pragma unroll
    for (int i = 0; i < 2; i++)
#pragma unroll
        for (int jn = 0; jn < 4; jn++) wmma::fill_fragment(acc[i][jn], 0.f);

    for (int chunk = 0; chunk < 9; chunk++) {
        // ---- stage A chunk (128 rows x 64 cols fp32 -> bf16 hi/lo)
        const int jj = chunk - 1;
        for (int idx = tid; idx < 2048; idx += 256) {
            int r = idx >> 4, c4 = idx & 15;
            float4 v;
            if (chunk == 0) {
                v = *reinterpret_cast<const float4*>(
                    q + (size_t)(c0 + r) * 64 + c4 * 4);
            } else if (jj < sN[r]) {
                size_t krow = (size_t)sBatch[r] * 512 + sIdx[r * 8 + jj];
                v = *reinterpret_cast<const float4*>(
                    kmat + krow * 64 + c4 * 4);
            } else {
                v = make_float4(0.f, 0.f, 0.f, 0.f);
            }
            float f[4] = {v.x, v.y, v.z, v.w};
            __nv_bfloat16 h[4], l[4];
#pragma unroll
            for (int e = 0; e < 4; e++) {
                h[e] = __float2bfloat16(f[e]);
                l[e] = __float2bfloat16(f[e] - __bfloat162float(h[e]));
            }
            __nv_bfloat162 h01; h01.x = h[0]; h01.y = h[1];
            __nv_bfloat162 h23; h23.x = h[2]; h23.y = h[3];
            __nv_bfloat162 l01; l01.x = l[0]; l01.y = l[1];
            __nv_bfloat162 l23; l23.x = l[2]; l23.y = l[3];
            __nv_bfloat162* ah = reinterpret_cast<__nv_bfloat162*>(Ah + r * A_LD + c4 * 4);
            __nv_bfloat162* al = reinterpret_cast<__nv_bfloat162*>(Al + r * A_LD + c4 * 4);
            ah[0] = h01; ah[1] = h23;
            al[0] = l01; al[1] = l23;
        }
        // ---- stage B chunk: W1 rows chunk*64 .. chunk*64+63 (pre-split)
        for (int idx = tid; idx < 1024; idx += 256) {
            int r = idx >> 4, c8 = idx & 15;
            size_t src = (size_t)(chunk * 64 + r) * 128 + c8 * 8;
            *reinterpret_cast<uint4*>(Bh + r * B_LD + c8 * 8) =
                *reinterpret_cast<const uint4*>(g_w1hi + src);
            *reinterpret_cast<uint4*>(Bl + r * B_LD + c8 * 8) =
                *reinterpret_cast<const uint4*>(g_w1lo + src);
        }
        __syncthreads();

#pragma unroll
        for (int k0 = 0; k0 < 64; k0 += 16) {
            wmma::fragment<wmma::matrix_a, 16, 16, 16, __nv_bfloat16,
                           wmma::row_major> fah[2], fal[2];
#pragma unroll
            for (int i = 0; i < 2; i++) {
                int ab = (wm * 32 + i * 16) * A_LD + k0;
                wmma::load_matrix_sync(fah[i], Ah + ab, A_LD);
                wmma::load_matrix_sync(fal[i], Al + ab, A_LD);
            }
#pragma unroll
            for (int jn = 0; jn < 4; jn++) {
                wmma::fragment<wmma::matrix_b, 16, 16, 16, __nv_bfloat16,
                               wmma::row_major> fbh, fbl;
                int bb = k0 * B_LD + wn * 64 + jn * 16;
                wmma::load_matrix_sync(fbh, Bh + bb, B_LD);
                wmma::load_matrix_sync(fbl, Bl + bb, B_LD);
#pragma unroll
                for (int i = 0; i < 2; i++) {
                    wmma::mma_sync(acc[i][jn], fah[i], fbh, acc[i][jn]);
                    wmma::mma_sync(acc[i][jn], fah[i], fbl, acc[i][jn]);
                    wmma::mma_sync(acc[i][jn], fal[i], fbh, acc[i][jn]);
                }
            }
        }
        __syncthreads();   // before next chunk overwrites A/B
    }

    // ---- epilogue: stage accs (aliased over A/B), then gelu + W2 dot
    float* so = reinterpret_cast<float*>(smem);
#pragma unroll
    for (int i = 0; i < 2; i++)
#pragma unroll
        for (int jn = 0; jn < 4; jn++)
            wmma::store_matrix_sync(
                so + (wm * 32 + i * 16) * STG_LD + wn * 64 + jn * 16,
                acc[i][jn], STG_LD, wmma::mem_row_major);
    __syncthreads();

    {
        const int row  = tid >> 1;          // 0..127
        const int half = tid & 1;           // 0..1 -> cols half*64..+63
        const float lc = sLogc[row];
        float p = 0.f;
#pragma unroll
        for (int c = 0; c < 64; c++) {
            int col = half * 64 + c;
            float x = so[row * STG_LD + col] + sB1[col] + lc * sWl[col];
            x = 0.5f * x * (1.0f + erff(x * 0.70710678118654752440f));
            p = fmaf(x, sW2[col], p);
        }
        p += __shfl_xor_sync(0xffffffffu, p, 1);
        if (half == 0) out[c0 + row] = p + b2[0];
    }
}

// ---------------------------------------------------------------------------
extern "C" void kernel_launch(void* const* d_in, const int* in_sizes, int n_in,
                              void* d_out, int out_size)
{
    const float* q         = (const float*)d_in[0];
    const float* kmat      = (const float*)d_in[1];
    const int*   batch_idx = (const int*)d_in[2];
    const int*   mask      = (const int*)d_in[3];
    const int*   count     = (const int*)d_in[4];
    const float* rank      = (const float*)d_in[5];
    const float* W1        = (const float*)d_in[6];
    const float* b1        = (const float*)d_in[7];
    const float* W2        = (const float*)d_in[8];
    const float* b2        = (const float*)d_in[9];
    float* out = (float*)d_out;

    cudaFuncSetAttribute(fused_mlp_kernel,
                         cudaFuncAttributeMaxDynamicSharedMemorySize, FUSED_SMEM);

    w1split_kernel<<<72, 256>>>(W1);
    select_kernel<<<2048, 256>>>(mask, rank);
    fused_mlp_kernel<<<512, 256, FUSED_SMEM>>>(
        q, kmat, batch_idx, count, W1, b1, W2, b2, out);
}

// round 13
// speedup vs baseline: 1.0513x; 1.0513x over previous
#include <cuda_runtime.h>
#include <cuda_bf16.h>
#include <cuda_pipeline_primitives.h>
#include <mma.h>
#include <float.h>
#include <math.h>
#include <stdint.h>

#define NCH 65536
#define BB  64
#define LL  512
#define MS  8
#define HID 128

__device__ int g_selidx[(size_t)NCH * MS];
__device__ int g_seln[NCH];
__device__ __align__(16) __nv_bfloat16 g_w1hi[577 * 128];
__device__ __align__(16) __nv_bfloat16 g_w1lo[577 * 128];
__device__ __align__(16) float g_zero4[4] = {0.f, 0.f, 0.f, 0.f};

using namespace nvcuda;

// order-preserving float->u32 (monotonic); masked entries use 0
__device__ __forceinline__ unsigned f2u(float f) {
    unsigned u = __float_as_uint(f);
    return (u & 0x80000000u) ? ~u : (u | 0x80000000u);
}

// ---------------------------------------------------------------------------
// W1 split: fp32 -> bf16 hi + lo (residual). Tiny.
// ---------------------------------------------------------------------------
__global__ void w1split_kernel(const float* __restrict__ W1)
{
    const int n = 577 * 128;
    for (int i = blockIdx.x * blockDim.x + threadIdx.x; i < n;
         i += gridDim.x * blockDim.x) {
        float f = W1[i];
        __nv_bfloat16 h = __float2bfloat16(f);
        g_w1hi[i] = h;
        g_w1lo[i] = __float2bfloat16(f - __bfloat162float(h));
    }
}

// ---------------------------------------------------------------------------
// Kernel 0: top-8 selection. grid 2048 x 256 thr; warp = 4 chains.
// ---------------------------------------------------------------------------
__global__ __launch_bounds__(256) void select_kernel(
    const int* __restrict__ mask, const float* __restrict__ rank)
{
    const int tid = threadIdx.x;
    const int w = tid >> 5, lane = tid & 31;
    const unsigned full = 0xffffffffu;

    for (int cc = 0; cc < 4; cc++) {
        const int chain = (blockIdx.x * 8 + w) * 4 + cc;
        const float* sc = rank + (size_t)chain * 512 + lane * 16;
        const int4*  mk = reinterpret_cast<const int4*>(
                              mask + (size_t)chain * 512) + lane * 4;
        unsigned key[16];
        unsigned m1 = 0, m2 = 0, m3 = 0;
        int p1 = 0, p2 = 0, p3 = 0;
        int cnt = 0;
#pragma unroll
        for (int g = 0; g < 4; g++) {
            int4   mw = mk[g];
            float4 s  = *reinterpret_cast<const float4*>(sc + g * 4);
            int   me[4] = {mw.x, mw.y, mw.z, mw.w};
            float vv[4] = {s.x, s.y, s.z, s.w};
#pragma unroll
            for (int e = 0; e < 4; e++) {
                const int i = g * 4 + e;
                bool mm = (me[e] != 0);
                unsigned k = mm ? f2u(vv[e]) : 0u;
                key[i] = k;
                cnt += mm ? 1 : 0;
                bool g1 = k > m1, g2 = k > m2, g3 = k > m3;
                m3 = g3 ? (g2 ? m2 : k) : m3;  p3 = g3 ? (g2 ? p2 : i) : p3;
                m2 = g2 ? (g1 ? m1 : k) : m2;  p2 = g2 ? (g1 ? p1 : i) : p2;
                m1 = g1 ? k : m1;              p1 = g1 ? i : p1;
            }
        }
        int tot  = __reduce_add_sync(full, cnt);
        int nsel = tot < 8 ? tot : 8;

        unsigned cons = 0;
#pragma unroll
        for (int t = 0; t < 8; t++) {
            unsigned m = __reduce_max_sync(full, m1);
            unsigned bal = __ballot_sync(full, m1 == m);
            int src = __ffs(bal) - 1;
            if (m != 0u && lane == src) {
                cons |= 1u << p1;
                m1 = m2; p1 = p2; m2 = m3; p2 = p3; m3 = 0; p3 = 0;
                if (m1 == 0u) {   // rare rescan
#pragma unroll
                    for (int i = 0; i < 16; i++) {
                        unsigned k = ((cons >> i) & 1u) ? 0u : key[i];
                        bool g1 = k > m1, g2 = k > m2, g3 = k > m3;
                        m3 = g3 ? (g2 ? m2 : k) : m3;  p3 = g3 ? (g2 ? p2 : i) : p3;
                        m2 = g2 ? (g1 ? m1 : k) : m2;  p2 = g2 ? (g1 ? p1 : i) : p2;
                        m1 = g1 ? k : m1;              p1 = g1 ? i : p1;
                    }
                }
            }
        }

        int my = __popc(cons);
        int pre = my;
#pragma unroll
        for (int off = 1; off < 32; off <<= 1) {
            int v = __shfl_up_sync(full, pre, off);
            if (lane >= off) pre += v;
        }
        pre -= my;
        if (lane == 0) g_seln[chain] = nsel;
        unsigned c = cons;
        int s = pre;
        while (c) {
            int i = __ffs(c) - 1;
            c &= c - 1;
            g_selidx[(size_t)chain * 8 + s] = lane * 16 + i;
            s++;
        }
    }
}

// ---------------------------------------------------------------------------
// Kernel 1 (fused, pipelined): full MLP per 128 chains. K=577 in 9 chunks;
// chunk 0 = q, chunks 1..8 = gathered k rows. A gather is async-copy
// double-buffered into a raw fp32 staging area (chunk c+1 issued before
// chunk c's MMA), converted to bf16 hi/lo from smem. WMMA bf16x3, fp32 acc.
// Invalid (jj >= nsel) rows copy from a zero buffer (no src-size tricks).
// ---------------------------------------------------------------------------
#define A_LD 72
#define B_LD 136
#define STG_LD 132
#define OFF_ARAW 0
#define OFF_AH 32768
#define OFF_AL 51200
#define OFF_BH 69632
#define OFF_BL 87040
#define OFF_META 104448
#define FUSED_SMEM (104448 + 7168)

__global__ __launch_bounds__(256, 2) void fused_mlp_kernel(
    const float* __restrict__ q,
    const float* __restrict__ kmat,
    const int*   __restrict__ batch_idx,
    const int*   __restrict__ count,
    const float* __restrict__ W1,
    const float* __restrict__ b1,
    const float* __restrict__ W2,
    const float* __restrict__ b2,
    float* __restrict__ out)
{
    extern __shared__ char smem[];
    float* Araw = reinterpret_cast<float*>(smem + OFF_ARAW);
    __nv_bfloat16* Ah = reinterpret_cast<__nv_bfloat16*>(smem + OFF_AH);
    __nv_bfloat16* Al = reinterpret_cast<__nv_bfloat16*>(smem + OFF_AL);
    __nv_bfloat16* Bh = reinterpret_cast<__nv_bfloat16*>(smem + OFF_BH);
    __nv_bfloat16* Bl = reinterpret_cast<__nv_bfloat16*>(smem + OFF_BL);
    int*   sBatch = reinterpret_cast<int*>(smem + OFF_META);
    int*   sN     = sBatch + 128;
    float* sLogc  = reinterpret_cast<float*>(sN + 128);
    int*   sIdx   = reinterpret_cast<int*>(sLogc + 128);       // [128][8]
    float* sB1    = reinterpret_cast<float*>(sIdx + 1024);
    float* sWl    = sB1 + 128;
    float* sW2    = sWl + 128;

    const int tid = threadIdx.x;
    const int c0  = blockIdx.x * 128;

    // ---- issue chunk 0 (q rows; needs no metadata) immediately
#pragma unroll
    for (int s = 0; s < 8; s++) {
        int idx = tid + 256 * s;
        int r = idx >> 4, c4 = idx & 15;
        __pipeline_memcpy_async(Araw + idx * 4,
                                q + (size_t)(c0 + r) * 64 + c4 * 4, 16);
    }
    __pipeline_commit();

    // ---- metadata staging (overlaps with async-copy flight)
    if (tid < 128) {
        sBatch[tid] = batch_idx[c0 + tid];
        sN[tid]     = g_seln[c0 + tid];
        sLogc[tid]  = log1pf((float)count[c0 + tid]);
        sB1[tid]    = b1[tid];
        sWl[tid]    = W1[576 * 128 + tid];
        sW2[tid]    = W2[tid];
    }
#pragma unroll
    for (int s = 0; s < 4; s++)
        sIdx[tid * 4 + s] = g_selidx[(size_t)c0 * 8 + tid * 4 + s];

    const int w  = tid >> 5;
    const int wm = w >> 1, wn = w & 1;

    wmma::fragment<wmma::accumulator, 16, 16, 16, float> acc[2][4];
#pragma unroll
    for (int i = 0; i < 2; i++)
#pragma unroll
        for (int jn = 0; jn < 4; jn++) wmma::fill_fragment(acc[i][jn], 0.f);

    for (int chunk = 0; chunk < 9; chunk++) {
        __pipeline_wait_prior(0);
        __syncthreads();   // (a) A_raw visible everywhere; prev MMA done

        // ---- stage B chunk (plain LDG -> STS; W1 hi/lo are L2-resident)
#pragma unroll
        for (int s = 0; s < 4; s++) {
            int idx = tid + 256 * s;
            int r = idx >> 4, c8 = idx & 15;
            size_t src = (size_t)(chunk * 64 + r) * 128 + c8 * 8;
            *reinterpret_cast<uint4*>(Bh + r * B_LD + c8 * 8) =
                *reinterpret_cast<const uint4*>(g_w1hi + src);
            *reinterpret_cast<uint4*>(Bl + r * B_LD + c8 * 8) =
                *reinterpret_cast<const uint4*>(g_w1lo + src);
        }
        // ---- convert A_raw (smem) -> bf16 hi/lo
#pragma unroll
        for (int s = 0; s < 8; s++) {
            int idx = tid + 256 * s;
            int r = idx >> 4, c4 = idx & 15;
            float4 v = *reinterpret_cast<const float4*>(Araw + idx * 4);
            float f[4] = {v.x, v.y, v.z, v.w};
            __nv_bfloat16 h[4], l[4];
#pragma unroll
            for (int e = 0; e < 4; e++) {
                h[e] = __float2bfloat16(f[e]);
                l[e] = __float2bfloat16(f[e] - __bfloat162float(h[e]));
            }
            __nv_bfloat162 h01; h01.x = h[0]; h01.y = h[1];
            __nv_bfloat162 h23; h23.x = h[2]; h23.y = h[3];
            __nv_bfloat162 l01; l01.x = l[0]; l01.y = l[1];
            __nv_bfloat162 l23; l23.x = l[2]; l23.y = l[3];
            __nv_bfloat162* ah = reinterpret_cast<__nv_bfloat162*>(Ah + r * A_LD + c4 * 4);
            __nv_bfloat162* al = reinterpret_cast<__nv_bfloat162*>(Al + r * A_LD + c4 * 4);
            ah[0] = h01; ah[1] = h23;
            al[0] = l01; al[1] = l23;
        }
        __syncthreads();   // (b) Ah/Al/Bh/Bl ready; A_raw free

        // ---- issue next chunk's gather; latency hides under MMA below
        if (chunk < 8) {
            const int jj = chunk;          // next chunk index - 1
#pragma unroll
            for (int s = 0; s < 8; s++) {
                int idx = tid + 256 * s;
                int r = idx >> 4, c4 = idx & 15;
                const float* src;
                if (jj < sN[r]) {
                    size_t krow = (size_t)sBatch[r] * 512 + sIdx[r * 8 + jj];
                    src = kmat + krow * 64 + c4 * 4;
                } else {
                    src = g_zero4;
                }
                __pipeline_memcpy_async(Araw + idx * 4, src, 16);
            }
            __pipeline_commit();
        }

        // ---- MMA for this chunk
#pragma unroll
        for (int k0 = 0; k0 < 64; k0 += 16) {
            wmma::fragment<wmma::matrix_a, 16, 16, 16, __nv_bfloat16,
                           wmma::row_major> fah[2], fal[2];
#pragma unroll
            for (int i = 0; i < 2; i++) {
                int ab = (wm * 32 + i * 16) * A_LD + k0;
                wmma::load_matrix_sync(fah[i], Ah + ab, A_LD);
                wmma::load_matrix_sync(fal[i], Al + ab, A_LD);
            }
#pragma unroll
            for (int jn = 0; jn < 4; jn++) {
                wmma::fragment<wmma::matrix_b, 16, 16, 16, __nv_bfloat16,
                               wmma::row_major> fbh, fbl;
                int bb = k0 * B_LD + wn * 64 + jn * 16;
                wmma::load_matrix_sync(fbh, Bh + bb, B_LD);
                wmma::load_matrix_sync(fbl, Bl + bb, B_LD);
#pragma unroll
                for (int i = 0; i < 2; i++) {
                    wmma::mma_sync(acc[i][jn], fah[i], fbh, acc[i][jn]);
                    wmma::mma_sync(acc[i][jn], fah[i], fbl, acc[i][jn]);
                    wmma::mma_sync(acc[i][jn], fal[i], fbh, acc[i][jn]);
                }
            }
        }
        // next iteration's sync (a) protects Ah/Bh against overwrite
    }
    __syncthreads();   // last MMA done before epilogue aliases A/B region

    // ---- epilogue: stage accs (aliased over A_raw/A/B), gelu + W2 dot
    float* so = reinterpret_cast<float*>(smem);
#pragma unroll
    for (int i = 0; i < 2; i++)
#pragma unroll
        for (int jn = 0; jn < 4; jn++)
            wmma::store_matrix_sync(
                so + (wm * 32 + i * 16) * STG_LD + wn * 64 + jn * 16,
                acc[i][jn], STG_LD, wmma::mem_row_major);
    __syncthreads();

    {
        const int row  = tid >> 1;          // 0..127
        const int half = tid & 1;           // cols half*64..+63
        const float lc = sLogc[row];
        float p = 0.f;
#pragma unroll
        for (int c = 0; c < 64; c++) {
            int col = half * 64 + c;
            float x = so[row * STG_LD + col] + sB1[col] + lc * sWl[col];
            x = 0.5f * x * (1.0f + erff(x * 0.70710678118654752440f));
            p = fmaf(x, sW2[col], p);
        }
        p += __shfl_xor_sync(0xffffffffu, p, 1);
        if (half == 0) out[c0 + row] = p + b2[0];
    }
}

// ---------------------------------------------------------------------------
extern "C" void kernel_launch(void* const* d_in, const int* in_sizes, int n_in,
                              void* d_out, int out_size)
{
    const float* q         = (const float*)d_in[0];
    const float* kmat      = (const float*)d_in[1];
    const int*   batch_idx = (const int*)d_in[2];
    const int*   mask      = (const int*)d_in[3];
    const int*   count     = (const int*)d_in[4];
    const float* rank      = (const float*)d_in[5];
    const float* W1        = (const float*)d_in[6];
    const float* b1        = (const float*)d_in[7];
    const float* W2        = (const float*)d_in[8];
    const float* b2        = (const float*)d_in[9];
    float* out = (float*)d_out;

    cudaFuncSetAttribute(fused_mlp_kernel,
                         cudaFuncAttributeMaxDynamicSharedMemorySize, FUSED_SMEM);

    w1split_kernel<<<72, 256>>>(W1);
    select_kernel<<<2048, 256>>>(mask, rank);
    fused_mlp_kernel<<<512, 256, FUSED_SMEM>>>(
        q, kmat, batch_idx, count, W1, b1, W2, b2, out);
}